// round 9
// baseline (speedup 1.0000x reference)
#include <cuda_runtime.h>
#include <math.h>
#include <stdint.h>

// ---------------------------------------------------------------------------
// TreeEncoder (binary Tree-LSTM reduction), tf32 tensor-core version.
//   leaf:  c = x@Wcx + bcx ; h = sigmoid(x@Wox + box) * tanh(c)
//   level: g = [lh|rh] @ [Wl;Wr] + bl + br ; gates -> c,h   (17 levels)
// out = [leaf_h (N*256) | c_root (256) | h_root (256)]
// All GEMM inputs pre-rounded to tf32 (cvt.rna) so the mma loop is pure HMMA.
// ---------------------------------------------------------------------------

#define NLEAF_MAX 131072
#define MD 256

__device__ float g_scratch[(size_t)NLEAF_MAX * 512];   // y (N x 512) or g (P x 1024)
__device__ float g_xt[(size_t)NLEAF_MAX * MD];         // x rounded to tf32
__device__ float g_cA[(size_t)NLEAF_MAX * MD];
__device__ float g_hA[(size_t)NLEAF_MAX * MD];
__device__ float g_cB[(size_t)(NLEAF_MAX / 2) * MD];
__device__ float g_hB[(size_t)(NLEAF_MAX / 2) * MD];
__device__ float g_Wleaf[256 * 512];                   // [Wcx | Wox], tf32-rounded
__device__ float g_Wnode[512 * 1024];                  // [Wl ; Wr], tf32-rounded
__device__ float g_bsum[1024];                         // bl + br

__device__ __forceinline__ float tf32r(float x) {
    uint32_t u;
    asm("cvt.rna.tf32.f32 %0, %1;" : "=r"(u) : "f"(x));
    return __uint_as_float(u);
}
__device__ __forceinline__ float sigmoidf(float v) {
    return 1.0f / (1.0f + expf(-v));
}

// ---- weight / bias packing (tf32-rounded weights) --------------------------
__global__ void pack_wleaf(const float* __restrict__ Wcx, const float* __restrict__ Wox) {
    int i = blockIdx.x * blockDim.x + threadIdx.x;
    if (i >= 256 * 512) return;
    int k = i >> 9, j = i & 511;
    float v = (j < 256) ? Wcx[k * 256 + j] : Wox[k * 256 + (j - 256)];
    g_Wleaf[i] = tf32r(v);
}

__global__ void pack_wnode(const float* __restrict__ Wl, const float* __restrict__ Wr) {
    int i = blockIdx.x * blockDim.x + threadIdx.x;
    if (i >= 512 * 1024) return;
    int k = i >> 10, j = i & 1023;
    float v = (k < 256) ? Wl[k * 1024 + j] : Wr[(k - 256) * 1024 + j];
    g_Wnode[i] = tf32r(v);
}

__global__ void pack_bias(const float* __restrict__ bl, const float* __restrict__ br) {
    int i = blockIdx.x * blockDim.x + threadIdx.x;
    if (i < 1024) g_bsum[i] = bl[i] + br[i];
}

__global__ void cvt_x(const float* __restrict__ x, float* __restrict__ xt, int n4) {
    int i = blockIdx.x * blockDim.x + threadIdx.x;
    if (i >= n4) return;
    float4 v = reinterpret_cast<const float4*>(x)[i];
    v.x = tf32r(v.x); v.y = tf32r(v.y); v.z = tf32r(v.z); v.w = tf32r(v.w);
    reinterpret_cast<float4*>(xt)[i] = v;
}

// ---- tf32 tensor-core GEMM -------------------------------------------------
// C[M,N] = A[M,K] @ B[K,N], fp32 storage holding tf32-rounded values.
// Block tile 128x128, BK=16, 8 warps (2x4), warp tile 64x32, mma m16n8k8.
// cp.async double-buffered. N % 128 == 0, K % 16 == 0. M arbitrary.

#define BM 128
#define BN 128
#define BKT 16
#define APITCH 20
#define BPITCH 136

__device__ __forceinline__ void cp16(uint32_t dst, const void* src, int sz) {
    asm volatile("cp.async.cg.shared.global [%0], [%1], 16, %2;\n"
                 :: "r"(dst), "l"(src), "r"(sz));
}
__device__ __forceinline__ void cp_commit() {
    asm volatile("cp.async.commit_group;\n");
}
template <int NW>
__device__ __forceinline__ void cp_wait() {
    asm volatile("cp.async.wait_group %0;\n" :: "n"(NW));
}

__global__ __launch_bounds__(256, 2)
void gemm_tf32(const float* __restrict__ A, const float* __restrict__ B,
               float* __restrict__ C, int M, int N, int K) {
    __shared__ float As[2][BM][APITCH];
    __shared__ float Bs[2][BKT][BPITCH];

    const int tid  = threadIdx.x;
    const int lane = tid & 31;
    const int warp = tid >> 5;
    const int g    = lane >> 2;      // group id 0..7
    const int t    = lane & 3;       // thread-in-group 0..3
    const int wm   = (warp & 1) * 64;
    const int wn   = (warp >> 1) * 32;
    const int row0 = blockIdx.y * BM;
    const int col0 = blockIdx.x * BN;

    uint32_t sA = (uint32_t)__cvta_generic_to_shared(&As[0][0][0]);
    uint32_t sB = (uint32_t)__cvta_generic_to_shared(&Bs[0][0][0]);

    float acc[4][4][4];
#pragma unroll
    for (int i = 0; i < 4; i++)
#pragma unroll
        for (int j = 0; j < 4; j++)
#pragma unroll
            for (int c = 0; c < 4; c++) acc[i][j][c] = 0.0f;

    const int nt = K / BKT;

    // Loader index precompute (2 float4s each for A and B per tile).
    int a_r[2], a_kq[2], b_k[2], b_nq[2];
#pragma unroll
    for (int i = 0; i < 2; i++) {
        int idx = tid + i * 256;
        a_r[i]  = idx >> 2;            // 0..127
        a_kq[i] = (idx & 3) << 2;      // 0,4,8,12
        b_k[i]  = idx >> 5;            // 0..15
        b_nq[i] = (idx & 31) << 2;     // 0..124
    }

#define ISSUE_TILE(STAGE, K0)                                                   \
    do {                                                                        \
        _Pragma("unroll")                                                       \
        for (int _i = 0; _i < 2; _i++) {                                        \
            int gr = row0 + a_r[_i];                                            \
            const float* src = A + (size_t)gr * K + (K0) + a_kq[_i];            \
            uint32_t dst = sA + (((STAGE) * BM + a_r[_i]) * APITCH + a_kq[_i]) * 4; \
            cp16(dst, src, (gr < M) ? 16 : 0);                                  \
        }                                                                       \
        _Pragma("unroll")                                                       \
        for (int _i = 0; _i < 2; _i++) {                                        \
            const float* src = B + (size_t)((K0) + b_k[_i]) * N + col0 + b_nq[_i]; \
            uint32_t dst = sB + (((STAGE) * BKT + b_k[_i]) * BPITCH + b_nq[_i]) * 4; \
            cp16(dst, src, 16);                                                 \
        }                                                                       \
        cp_commit();                                                            \
    } while (0)

    ISSUE_TILE(0, 0);

    for (int tI = 0; tI < nt; tI++) {
        if (tI + 1 < nt) {
            ISSUE_TILE((tI + 1) & 1, (tI + 1) * BKT);
            cp_wait<1>();
        } else {
            cp_wait<0>();
        }
        __syncthreads();

        const int s = tI & 1;
#pragma unroll
        for (int kk = 0; kk < 2; kk++) {
            const int kb = kk * 8;
            uint32_t a[4][4], b[4][2];
#pragma unroll
            for (int i = 0; i < 4; i++) {
                const float* ap = &As[s][wm + i * 16 + g][kb + t];
                a[i][0] = __float_as_uint(ap[0]);
                a[i][1] = __float_as_uint(ap[8 * APITCH]);
                a[i][2] = __float_as_uint(ap[4]);
                a[i][3] = __float_as_uint(ap[8 * APITCH + 4]);
            }
#pragma unroll
            for (int j = 0; j < 4; j++) {
                const float* bp = &Bs[s][kb + t][wn + j * 8 + g];
                b[j][0] = __float_as_uint(bp[0]);
                b[j][1] = __float_as_uint(bp[4 * BPITCH]);
            }
#pragma unroll
            for (int i = 0; i < 4; i++)
#pragma unroll
                for (int j = 0; j < 4; j++)
                    asm volatile(
                        "mma.sync.aligned.m16n8k8.row.col.f32.tf32.tf32.f32 "
                        "{%0,%1,%2,%3}, {%4,%5,%6,%7}, {%8,%9}, {%0,%1,%2,%3};"
                        : "+f"(acc[i][j][0]), "+f"(acc[i][j][1]),
                          "+f"(acc[i][j][2]), "+f"(acc[i][j][3])
                        : "r"(a[i][0]), "r"(a[i][1]), "r"(a[i][2]), "r"(a[i][3]),
                          "r"(b[j][0]), "r"(b[j][1]));
        }
        __syncthreads();
    }

    // Store C: per frag, rows (r, r+8), cols 2t,2t+1 -> float2 stores.
#pragma unroll
    for (int i = 0; i < 4; i++) {
        int r = row0 + wm + i * 16 + g;
#pragma unroll
        for (int j = 0; j < 4; j++) {
            int cb = col0 + wn + j * 8 + t * 2;
            if (r < M)
                *reinterpret_cast<float2*>(&C[(size_t)r * N + cb]) =
                    make_float2(acc[i][j][0], acc[i][j][1]);
            if (r + 8 < M)
                *reinterpret_cast<float2*>(&C[(size_t)(r + 8) * N + cb]) =
                    make_float2(acc[i][j][2], acc[i][j][3]);
        }
    }
#undef ISSUE_TILE
}

// ---- leaf epilogue (float4) ------------------------------------------------
// y: [M,512]. c full precision; h buffer tf32-rounded (GEMM input); out full.
__global__ void leaf_epi4(const float* __restrict__ y,
                          const float* __restrict__ bcx, const float* __restrict__ box_,
                          float* __restrict__ c, float* __restrict__ h,
                          float* __restrict__ out, int M) {
    size_t i = (size_t)blockIdx.x * blockDim.x + threadIdx.x;
    if (i >= (size_t)M * 64) return;
    size_t p = i >> 6;
    int jj = (int)(i & 63) << 2;
    float4 cv = *reinterpret_cast<const float4*>(&y[p * 512 + jj]);
    float4 ov = *reinterpret_cast<const float4*>(&y[p * 512 + 256 + jj]);
    float4 bc = *reinterpret_cast<const float4*>(&bcx[jj]);
    float4 bo = *reinterpret_cast<const float4*>(&box_[jj]);
    cv.x += bc.x; cv.y += bc.y; cv.z += bc.z; cv.w += bc.w;
    float4 hv;
    hv.x = sigmoidf(ov.x + bo.x) * tanhf(cv.x);
    hv.y = sigmoidf(ov.y + bo.y) * tanhf(cv.y);
    hv.z = sigmoidf(ov.z + bo.z) * tanhf(cv.z);
    hv.w = sigmoidf(ov.w + bo.w) * tanhf(cv.w);
    *reinterpret_cast<float4*>(&c[p * 256 + jj]) = cv;
    *reinterpret_cast<float4*>(&out[p * 256 + jj]) = hv;
    float4 hr;
    hr.x = tf32r(hv.x); hr.y = tf32r(hv.y); hr.z = tf32r(hv.z); hr.w = tf32r(hv.w);
    *reinterpret_cast<float4*>(&h[p * 256 + jj]) = hr;
}

// ---- node epilogue (float4) ------------------------------------------------
__global__ void node_epi4(const float* __restrict__ gmat,
                          const float* __restrict__ c_prev,
                          float* __restrict__ c_new, float* __restrict__ h_new, int P) {
    size_t i = (size_t)blockIdx.x * blockDim.x + threadIdx.x;
    if (i >= (size_t)P * 64) return;
    size_t p = i >> 6;
    int jj = (int)(i & 63) << 2;
    const float* gr = gmat + p * 1024;
    float4 gi  = *reinterpret_cast<const float4*>(&gr[jj]);
    float4 glf = *reinterpret_cast<const float4*>(&gr[256 + jj]);
    float4 grf = *reinterpret_cast<const float4*>(&gr[512 + jj]);
    float4 gu  = *reinterpret_cast<const float4*>(&gr[768 + jj]);
    float4 b0 = *reinterpret_cast<const float4*>(&g_bsum[jj]);
    float4 b1 = *reinterpret_cast<const float4*>(&g_bsum[256 + jj]);
    float4 b2 = *reinterpret_cast<const float4*>(&g_bsum[512 + jj]);
    float4 b3 = *reinterpret_cast<const float4*>(&g_bsum[768 + jj]);
    float4 lc = *reinterpret_cast<const float4*>(&c_prev[p * 512 + jj]);
    float4 rc = *reinterpret_cast<const float4*>(&c_prev[p * 512 + 256 + jj]);

    float4 cv, hr;
#define GATE(X)                                                                 \
    {                                                                           \
        float iv = sigmoidf(gi.X + b0.X);                                       \
        float lf = sigmoidf(glf.X + b1.X);                                      \
        float rf = sigmoidf(grf.X + b2.X);                                      \
        float u  = tanhf(gu.X + b3.X);                                          \
        cv.X = iv * u + lf * lc.X + rf * rc.X;                                  \
        hr.X = tf32r(tanhf(cv.X));                                              \
    }
    GATE(x) GATE(y) GATE(z) GATE(w)
#undef GATE
    *reinterpret_cast<float4*>(&c_new[p * 256 + jj]) = cv;
    *reinterpret_cast<float4*>(&h_new[p * 256 + jj]) = hr;
}

// ---- root copy: c_root full precision; h_root recomputed = tanh(c_root) ----
__global__ void copy_roots(const float* __restrict__ c, float* __restrict__ dst) {
    int j = threadIdx.x;  // 256 threads
    float cv = c[j];
    dst[j] = cv;
    dst[256 + j] = tanhf(cv);
}

// ---------------------------------------------------------------------------
extern "C" void kernel_launch(void* const* d_in, const int* in_sizes, int n_in,
                              void* d_out, int out_size) {
    const float* x    = (const float*)d_in[0];
    const float* Wcx  = (const float*)d_in[1];
    const float* bcx  = (const float*)d_in[2];
    const float* Wox  = (const float*)d_in[3];
    const float* box_ = (const float*)d_in[4];
    const float* Wl   = (const float*)d_in[5];
    const float* bl   = (const float*)d_in[6];
    const float* Wr   = (const float*)d_in[7];
    const float* br   = (const float*)d_in[8];

    const int M = in_sizes[0] / 256;  // number of leaves (131072)

    float *scratch, *xt, *cA, *hA, *cB, *hB, *Wleaf, *Wnode;
    cudaGetSymbolAddress((void**)&scratch, g_scratch);
    cudaGetSymbolAddress((void**)&xt, g_xt);
    cudaGetSymbolAddress((void**)&cA, g_cA);
    cudaGetSymbolAddress((void**)&hA, g_hA);
    cudaGetSymbolAddress((void**)&cB, g_cB);
    cudaGetSymbolAddress((void**)&hB, g_hB);
    cudaGetSymbolAddress((void**)&Wleaf, g_Wleaf);
    cudaGetSymbolAddress((void**)&Wnode, g_Wnode);

    float* out = (float*)d_out;

    // Pack weights (tf32-rounded), bias sums, rounded x.
    pack_wleaf<<<(256 * 512 + 255) / 256, 256>>>(Wcx, Wox);
    pack_wnode<<<(512 * 1024 + 255) / 256, 256>>>(Wl, Wr);
    pack_bias<<<4, 256>>>(bl, br);
    {
        int n4 = M * 256 / 4;
        cvt_x<<<(n4 + 255) / 256, 256>>>(x, xt, n4);
    }

    // Leaf stage: y = x_tf32 @ [Wcx|Wox]  (M x 512, K=256)
    {
        dim3 grid(512 / BN, (M + BM - 1) / BM);
        gemm_tf32<<<grid, 256>>>(xt, Wleaf, scratch, M, 512, 256);
        size_t groups = (size_t)M * 64;
        leaf_epi4<<<(unsigned)((groups + 255) / 256), 256>>>(
            scratch, bcx, box_, cA, hA, out, M);
    }

    // Tree reduction: 17 levels, ping-pong c/h buffers.
    float* cin = cA;  float* hin = hA;
    float* cout_ = cB; float* hout_ = hB;
    int n = M;
    while (n > 1) {
        int P = n / 2;
        dim3 grid(1024 / BN, (P + BM - 1) / BM);
        gemm_tf32<<<grid, 256>>>(hin, Wnode, scratch, P, 1024, 512);
        size_t groups = (size_t)P * 64;
        node_epi4<<<(unsigned)((groups + 255) / 256), 256>>>(
            scratch, cin, cout_, hout_, P);
        float* tp;
        tp = cin; cin = cout_; cout_ = tp;
        tp = hin; hin = hout_; hout_ = tp;
        n = P;
    }

    copy_roots<<<1, 256>>>(cin, out + (size_t)M * MD);
}